// round 12
// baseline (speedup 1.0000x reference)
#include <cuda_runtime.h>
#include <cuda_bf16.h>
#include <cstdint>

#define NPTS 12288
#define DIM 16
#define NT 96                         // number of 128-point tiles
#define NPAIRS (NT * (NT + 1) / 2)    // 4656 triangle tiles
#define TPB 256
#define SOP_BLK 256
#define SOP_BLOCKS (NPTS / SOP_BLK)   // 48
#define RPAD 132                      // rowpart row stride (bank-conflict pad)

typedef unsigned long long u64;

// ---- scratch (__device__ globals; no allocation allowed) ------------------
// g_partT[p*NT + s] = (se, sw) contribution to point p from tile s's 128
// partners. TRANSPOSED layout: per-point slots contiguous -> sop reduces with
// coalesced float4 loads. Each (p,s) written by exactly ONE block (row-path
// if tile(p) <= s, col-path if s < tile(p)). Deterministic, no atomics.
__device__ __align__(16) float2 g_partT[NPTS * NT];   // 9.4 MB
__device__ float g_Mpart[SOP_BLOCKS][256];            // per-block SOP partials
__device__ unsigned int g_cnt = 0;                    // last-block counter (self-resetting)

__device__ __forceinline__ float ex2_approx(float x) {
    float r; asm("ex2.approx.ftz.f32 %0, %1;" : "=f"(r) : "f"(x)); return r;
}
__device__ __forceinline__ uint32_t bf2_u32(__nv_bfloat162 v) {
    return *reinterpret_cast<uint32_t*>(&v);
}
__device__ __forceinline__ u64 pack2(float lo, float hi) {
    u64 r; asm("mov.b64 %0, {%1, %2};" : "=l"(r) : "f"(lo), "f"(hi)); return r;
}
__device__ __forceinline__ void unpack2(u64 v, float& lo, float& hi) {
    asm("mov.b64 {%0, %1}, %2;" : "=f"(lo), "=f"(hi) : "l"(v));
}
__device__ __forceinline__ u64 add2(u64 a, u64 b) {
    u64 d; asm("add.rn.f32x2 %0, %1, %2;" : "=l"(d) : "l"(a), "l"(b)); return d;
}

// ---------------------------------------------------------------------------
// Kernel 1: symmetric tiled attention stats, packed-f32x2 epilogue.
// Block = one 128x128 tile (i,j), i<=j; each exp serves BOTH its row and its
// column stats (half the exps of dense). Per score: e = 2^t, ep = {e, e*t}
// accumulated with add.rn.f32x2. Warp owns 16 keys (B frags loaded once);
// col sums live in registers; row partials go STRAIGHT to tig-resolved smem
// (2 STS.64 per row-group, no in-loop shuffles) and are reduced once at the
// end (conflict-free LDS.64). Identity: <ctx_q,f_q> = 4*ln2 * sw_q/se_q.
// ---------------------------------------------------------------------------
__global__ void __launch_bounds__(TPB) attn_tile_kernel(const float* __restrict__ feats) {
    __shared__ uint32_t sA[128 * 12];       // queries bf16x2, scaled (stride-12: conflict-free)
    __shared__ uint32_t sB[128 * 12];       // keys bf16x2, unscaled
    __shared__ u64 rowpart[8 * 4 * RPAD];   // [warp][tig][row(+pad)] packed partials, 33.8 KB
    __shared__ u64 tmpred[128];             // half-combine scratch

    // decode linear block id -> triangle tile (i, j), i <= j
    int i = 0, rem = blockIdx.x;
    while (rem >= NT - i) { rem -= NT - i; i++; }
    const int j = i + rem;
    const bool diag = (i == j);

    const int tid  = threadIdx.x;
    const int warp = tid >> 5;
    const int lane = tid & 31;
    const int g    = lane >> 2;             // 0..7
    const int tig  = lane & 3;              // 0..3

    // ---- stage both tiles, converting f32 -> bf16 on the fly ----
    {
        const float sc = 0.25f * 1.4426950408889634f;
        const float4* fa = reinterpret_cast<const float4*>(feats) + i * 128 * 4;
        const float4* fb = reinterpret_cast<const float4*>(feats) + j * 128 * 4;
        #pragma unroll
        for (int t = tid; t < 512; t += TPB) {
            int row = t >> 2, f = t & 3;
            float4 va = fa[t];
            float4 vb = fb[t];
            uint2 ua = make_uint2(bf2_u32(__floats2bfloat162_rn(va.x * sc, va.y * sc)),
                                  bf2_u32(__floats2bfloat162_rn(va.z * sc, va.w * sc)));
            uint2 ub = make_uint2(bf2_u32(__floats2bfloat162_rn(vb.x, vb.y)),
                                  bf2_u32(__floats2bfloat162_rn(vb.z, vb.w)));
            *reinterpret_cast<uint2*>(&sA[row * 12 + 2 * f]) = ua;
            *reinterpret_cast<uint2*>(&sB[row * 12 + 2 * f]) = ub;
        }
    }
    __syncthreads();

    // ---- B fragments for this warp's 16 keys (loaded once) ----
    const int wkey = warp * 16;
    const uint32_t b00 = sB[(wkey + g) * 12 + tig];
    const uint32_t b01 = sB[(wkey + g) * 12 + tig + 4];
    const uint32_t b10 = sB[(wkey + 8 + g) * 12 + tig];
    const uint32_t b11 = sB[(wkey + 8 + g) * 12 + tig + 4];

    // packed col accumulators {se, sw}: keys wkey + {2tig, 2tig+1, 8+2tig, 9+2tig}
    u64 c0 = pack2(0.f, 0.f), c1 = c0, c2 = c0, c3 = c0;

    u64* myrow = &rowpart[(warp * 4 + tig) * RPAD];

    #pragma unroll
    for (int rg = 0; rg < 8; rg++) {
        const int r0 = rg * 16;
        uint32_t a0 = sA[(r0 + g) * 12 + tig];
        uint32_t a1 = sA[(r0 + 8 + g) * 12 + tig];
        uint32_t a2 = sA[(r0 + g) * 12 + tig + 4];
        uint32_t a3 = sA[(r0 + 8 + g) * 12 + tig + 4];

        u64 row0, row1;   // packed row partials for rows r0+g, r0+8+g
        {   // MMA 1: keys wkey + 2tig, wkey + 2tig + 1
            float d0, d1, d2, d3;
            asm volatile(
                "mma.sync.aligned.m16n8k16.row.col.f32.bf16.bf16.f32 "
                "{%0,%1,%2,%3}, {%4,%5,%6,%7}, {%8,%9}, {%10,%11,%12,%13};"
                : "=f"(d0), "=f"(d1), "=f"(d2), "=f"(d3)
                : "r"(a0), "r"(a1), "r"(a2), "r"(a3), "r"(b00), "r"(b01),
                  "f"(0.0f), "f"(0.0f), "f"(0.0f), "f"(0.0f));
            float e0 = ex2_approx(d0), e1 = ex2_approx(d1);
            float e2 = ex2_approx(d2), e3 = ex2_approx(d3);
            u64 ep0 = pack2(e0, e0 * d0);
            u64 ep1 = pack2(e1, e1 * d1);
            u64 ep2 = pack2(e2, e2 * d2);
            u64 ep3 = pack2(e3, e3 * d3);
            row0 = add2(ep0, ep1);          // row r0+g
            row1 = add2(ep2, ep3);          // row r0+8+g
            c0 = add2(c0, add2(ep0, ep2));  // key wkey+2tig
            c1 = add2(c1, add2(ep1, ep3));  // key wkey+2tig+1
        }
        {   // MMA 2: keys wkey + 8 + 2tig, wkey + 9 + 2tig
            float d0, d1, d2, d3;
            asm volatile(
                "mma.sync.aligned.m16n8k16.row.col.f32.bf16.bf16.f32 "
                "{%0,%1,%2,%3}, {%4,%5,%6,%7}, {%8,%9}, {%10,%11,%12,%13};"
                : "=f"(d0), "=f"(d1), "=f"(d2), "=f"(d3)
                : "r"(a0), "r"(a1), "r"(a2), "r"(a3), "r"(b10), "r"(b11),
                  "f"(0.0f), "f"(0.0f), "f"(0.0f), "f"(0.0f));
            float e0 = ex2_approx(d0), e1 = ex2_approx(d1);
            float e2 = ex2_approx(d2), e3 = ex2_approx(d3);
            u64 ep0 = pack2(e0, e0 * d0);
            u64 ep1 = pack2(e1, e1 * d1);
            u64 ep2 = pack2(e2, e2 * d2);
            u64 ep3 = pack2(e3, e3 * d3);
            row0 = add2(row0, add2(ep0, ep1));
            row1 = add2(row1, add2(ep2, ep3));
            c2 = add2(c2, add2(ep0, ep2));  // key wkey+8+2tig
            c3 = add2(c3, add2(ep1, ep3));  // key wkey+9+2tig
        }

        // per-thread row partials straight to smem (no shuffles)
        myrow[r0 + g]     = row0;
        myrow[r0 + 8 + g] = row1;
    }
    __syncthreads();

    // ---- row stats: reduce rowpart over (warp, tig) -> slot j ----
    {
        const int row  = tid & 127;
        const int half = tid >> 7;          // 0: warps 0-3, 1: warps 4-7
        u64 acc = rowpart[(half * 16) * RPAD + row];
        #pragma unroll
        for (int k = 1; k < 16; k++)
            acc = add2(acc, rowpart[(half * 16 + k) * RPAD + row]);
        if (half == 1) tmpred[row] = acc;
        __syncthreads();
        if (half == 0) {
            acc = add2(acc, tmpred[row]);
            float se, sw;
            unpack2(acc, se, sw);
            g_partT[(i * 128 + row) * NT + j] = make_float2(se, sw);
        }
    }

    // ---- col stats: reduce over the 8 g-groups -> slot i (skip on diag) ----
    if (!diag) {
        #pragma unroll
        for (int m = 4; m <= 16; m <<= 1) {
            c0 = add2(c0, __shfl_xor_sync(0xffffffffu, c0, m));
            c1 = add2(c1, __shfl_xor_sync(0xffffffffu, c1, m));
            c2 = add2(c2, __shfl_xor_sync(0xffffffffu, c2, m));
            c3 = add2(c3, __shfl_xor_sync(0xffffffffu, c3, m));
        }
        if (g == 0) {
            const int kb = j * 128 + wkey;
            float se, sw;
            unpack2(c0, se, sw); g_partT[(kb + 2 * tig)     * NT + i] = make_float2(se, sw);
            unpack2(c1, se, sw); g_partT[(kb + 2 * tig + 1) * NT + i] = make_float2(se, sw);
            unpack2(c2, se, sw); g_partT[(kb + 8 + 2 * tig) * NT + i] = make_float2(se, sw);
            unpack2(c3, se, sw); g_partT[(kb + 9 + 2 * tig) * NT + i] = make_float2(se, sw);
        }
    }
}

// ---------------------------------------------------------------------------
// Kernel 2: reduce this point's 96 contiguous slots (coalesced float4),
// w = sigmoid(4*ln2 * sw/se); block-local SOP partial
// M_b = sum_i w_i^2 f_i f_i^T; LAST block (atomic counter) reduces partials,
// L2-normalizes, writes 256-float output.
// (topK=1 -> all points kept; /k cancels in the L2-normalize.)
// ---------------------------------------------------------------------------
__global__ void __launch_bounds__(SOP_BLK) sop_kernel(const float* __restrict__ feats,
                                                      float* __restrict__ out) {
    __shared__ float sf[SOP_BLK][DIM];
    __shared__ float sw2[SOP_BLK];
    __shared__ unsigned int isLast;

    const int tid = threadIdx.x;
    const int b   = blockIdx.x;
    const int p   = b * SOP_BLK + tid;

    // contiguous per-point slot reduction: 48 float4 = 96 float2
    float se = 0.0f, sw = 0.0f;
    {
        const float4* gp = reinterpret_cast<const float4*>(&g_partT[p * NT]);
        #pragma unroll 16
        for (int s = 0; s < NT / 2; s++) {
            float4 v = gp[s];
            se += v.x + v.z;
            sw += v.y + v.w;
        }
    }
    const float c4ln2 = 4.0f * 0.6931471805599453f;
    float cf = c4ln2 * sw / se;
    float w = 1.0f / (1.0f + __expf(-cf));
    sw2[tid] = w * w;

    const float4* fp = reinterpret_cast<const float4*>(feats) + p * 4;
    float4 f0 = fp[0], f1 = fp[1], f2 = fp[2], f3 = fp[3];
    sf[tid][0]  = f0.x; sf[tid][1]  = f0.y; sf[tid][2]  = f0.z; sf[tid][3]  = f0.w;
    sf[tid][4]  = f1.x; sf[tid][5]  = f1.y; sf[tid][6]  = f1.z; sf[tid][7]  = f1.w;
    sf[tid][8]  = f2.x; sf[tid][9]  = f2.y; sf[tid][10] = f2.z; sf[tid][11] = f2.w;
    sf[tid][12] = f3.x; sf[tid][13] = f3.y; sf[tid][14] = f3.z; sf[tid][15] = f3.w;
    __syncthreads();

    const int d = tid >> 4;
    const int e = tid & 15;
    float acc = 0.0f;
    #pragma unroll 8
    for (int i = 0; i < SOP_BLK; i++) {
        acc = fmaf(sw2[i] * sf[i][d], sf[i][e], acc);
    }
    g_Mpart[b][tid] = acc;

    // ---- last-block finalize (deterministic; counter self-resets) ----
    __threadfence();
    if (tid == 0) isLast = (atomicAdd(&g_cnt, 1u) == SOP_BLOCKS - 1) ? 1u : 0u;
    __syncthreads();
    if (isLast) {
        __threadfence();
        float v = 0.0f;
        #pragma unroll 8
        for (int bb = 0; bb < SOP_BLOCKS; bb++) v += g_Mpart[bb][tid];

        __syncthreads();          // sw2 reuse safe
        sw2[tid] = v * v;
        __syncthreads();
        #pragma unroll
        for (int o = 128; o > 0; o >>= 1) {
            if (tid < o) sw2[tid] += sw2[tid + o];
            __syncthreads();
        }
        float inv = 1.0f / sqrtf(sw2[0]);
        out[tid] = v * inv;
        if (tid == 0) g_cnt = 0;
    }
}

// ---------------------------------------------------------------------------
extern "C" void kernel_launch(void* const* d_in, const int* in_sizes, int n_in,
                              void* d_out, int out_size) {
    const float* feats = (const float*)d_in[0];
    float* out = (float*)d_out;

    attn_tile_kernel<<<NPAIRS, TPB>>>(feats);
    sop_kernel<<<SOP_BLOCKS, SOP_BLK>>>(feats, out);
}

// round 13
// speedup vs baseline: 1.1825x; 1.1825x over previous
#include <cuda_runtime.h>
#include <cuda_bf16.h>
#include <cstdint>

#define NPTS 12288
#define DIM 16
#define KSPLIT 6
#define QT_TILES 96                     // 12288/128 query tiles
#define TPB 256
#define KEYS_PER_SPLIT (NPTS / KSPLIT)  // 2048
#define KEYTILE 512
#define TILES (KEYS_PER_SPLIT / KEYTILE)// 4
#define SOP_BLK 256
#define SOP_BLOCKS (NPTS / SOP_BLK)     // 48

// ---- scratch (__device__ globals; no allocation allowed) ------------------
__device__ float g_se[KSPLIT][NPTS];        // exp-sum partials
__device__ float g_sw[KSPLIT][NPTS];        // exp*score-sum partials (log2-units)
__device__ float g_Mpart[SOP_BLOCKS][256];  // per-block SOP partials
__device__ unsigned int g_cnt = 0;          // last-block counter (self-resetting)

__device__ __forceinline__ float ex2_approx(float x) {
    float r; asm("ex2.approx.ftz.f32 %0, %1;" : "=f"(r) : "f"(x)); return r;
}
// fma-pipe 2^t: linear-mantissa approximation (±2% ripple, mean bias cancels
// in the sw/se ratio; 50/50 alternation with MUFU kills the systematic part).
__device__ __forceinline__ float bexp2(float t) {
    float f = fmaf(t, 8388608.0f, 1065353216.0f);   // t*2^23 + 127*2^23
    return __int_as_float((int)f);
}
__device__ __forceinline__ uint32_t bf2_u32(__nv_bfloat162 v) {
    return *reinterpret_cast<uint32_t*>(&v);
}

// ---------------------------------------------------------------------------
// Kernel 1: dense tensor-core attention row stats (R9 structure), with
// (a) on-the-fly f32->bf16 conversion (no separate convert kernel) and
// (b) hybrid exp: per MMA, one row-half uses MUFU ex2, the other the
//     fma-pipe bit-trick; roles alternate with key-iteration parity.
// Warp owns 16 queries (A frags built once from feats, pre-scaled by
// 0.25*log2 e); loops over 512-key smem tiles (48B/key stride ->
// conflict-free). Per score: e = 2^t; se += e; sw += e*t.
// Identity: <ctx_q,f_q> = 4*ln2 * sw_q/se_q -> no ctx materialization.
// ---------------------------------------------------------------------------
__global__ void __launch_bounds__(TPB, 4) attn_mma_kernel(const float* __restrict__ feats) {
    __shared__ uint32_t sk[KEYTILE * 12];   // 24 KB, 48B per key (12 words)

    const int tid  = threadIdx.x;
    const int warp = tid >> 5;
    const int lane = tid & 31;
    const int g    = lane >> 2;             // 0..7
    const int tig  = lane & 3;              // 0..3
    const int qt    = blockIdx.x % QT_TILES;
    const int split = blockIdx.x / QT_TILES;

    const int q0 = qt * 128 + warp * 16 + g;
    const int q1 = q0 + 8;

    // A fragments straight from feats (scaled f32 -> bf16x2)
    const float sc = 0.25f * 1.4426950408889634f;
    const float2* f2 = reinterpret_cast<const float2*>(feats);
    float2 v00 = f2[q0 * 8 + tig];
    float2 v02 = f2[q0 * 8 + tig + 4];
    float2 v10 = f2[q1 * 8 + tig];
    float2 v12 = f2[q1 * 8 + tig + 4];
    const uint32_t a0 = bf2_u32(__floats2bfloat162_rn(v00.x * sc, v00.y * sc));
    const uint32_t a1 = bf2_u32(__floats2bfloat162_rn(v10.x * sc, v10.y * sc));
    const uint32_t a2 = bf2_u32(__floats2bfloat162_rn(v02.x * sc, v02.y * sc));
    const uint32_t a3 = bf2_u32(__floats2bfloat162_rn(v12.x * sc, v12.y * sc));

    float se0 = 0.0f, se1 = 0.0f, sw0 = 0.0f, sw1 = 0.0f;

    const int key0 = split * KEYS_PER_SPLIT;

    for (int tile = 0; tile < TILES; tile++) {
        __syncthreads();
        // stage 512 keys, converting f32 -> bf16 (48B/key smem stride)
        {
            const float4* src = reinterpret_cast<const float4*>(feats)
                              + (key0 + tile * KEYTILE) * 4;
            #pragma unroll
            for (int idx = tid; idx < KEYTILE * 4; idx += TPB) {
                int key = idx >> 2, quad = idx & 3;
                float4 v = src[idx];
                uint2 u = make_uint2(bf2_u32(__floats2bfloat162_rn(v.x, v.y)),
                                     bf2_u32(__floats2bfloat162_rn(v.z, v.w)));
                *reinterpret_cast<uint2*>(&sk[key * 12 + quad * 2]) = u;
            }
        }
        __syncthreads();

        #pragma unroll 4
        for (int j = 0; j < KEYTILE / 8; j++) {
            const int kb = j * 8 + g;       // this thread's B-fragment key
            uint32_t b0 = sk[kb * 12 + tig];
            uint32_t b1 = sk[kb * 12 + tig + 4];

            float d0, d1, d2, d3;
            asm volatile(
                "mma.sync.aligned.m16n8k16.row.col.f32.bf16.bf16.f32 "
                "{%0,%1,%2,%3}, {%4,%5,%6,%7}, {%8,%9}, {%10,%11,%12,%13};"
                : "=f"(d0), "=f"(d1), "=f"(d2), "=f"(d3)
                : "r"(a0), "r"(a1), "r"(a2), "r"(a3), "r"(b0), "r"(b1),
                  "f"(0.0f), "f"(0.0f), "f"(0.0f), "f"(0.0f));

            // d0,d1: row q0 (keys 2tig,2tig+1); d2,d3: row q1
            // hybrid exp, roles alternating with j parity
            float e0, e1, e2, e3;
            if (j & 1) {
                e0 = bexp2(d0);      e1 = bexp2(d1);
                e2 = ex2_approx(d2); e3 = ex2_approx(d3);
            } else {
                e0 = ex2_approx(d0); e1 = ex2_approx(d1);
                e2 = bexp2(d2);      e3 = bexp2(d3);
            }
            se0 += e0; sw0 = fmaf(e0, d0, sw0);
            se0 += e1; sw0 = fmaf(e1, d1, sw0);
            se1 += e2; sw1 = fmaf(e2, d2, sw1);
            se1 += e3; sw1 = fmaf(e3, d3, sw1);
        }
    }

    // reduce across the 4 threads of each row-quad (tids 4g..4g+3)
    se0 += __shfl_xor_sync(0xffffffffu, se0, 1);
    se0 += __shfl_xor_sync(0xffffffffu, se0, 2);
    se1 += __shfl_xor_sync(0xffffffffu, se1, 1);
    se1 += __shfl_xor_sync(0xffffffffu, se1, 2);
    sw0 += __shfl_xor_sync(0xffffffffu, sw0, 1);
    sw0 += __shfl_xor_sync(0xffffffffu, sw0, 2);
    sw1 += __shfl_xor_sync(0xffffffffu, sw1, 1);
    sw1 += __shfl_xor_sync(0xffffffffu, sw1, 2);

    if (tig == 0) {
        g_se[split][q0] = se0;
        g_sw[split][q0] = sw0;
        g_se[split][q1] = se1;
        g_sw[split][q1] = sw1;
    }
}

// ---------------------------------------------------------------------------
// Kernel 2: w = sigmoid(4*ln2 * sw/se); block-local SOP partial
// M_b = sum_i w_i^2 f_i f_i^T, then the LAST block (atomic counter) reduces
// all partials, L2-normalizes, writes the 256-float output, resets counter.
// (topK=1 -> all points kept; /k cancels in the L2-normalize.)
// ---------------------------------------------------------------------------
__global__ void __launch_bounds__(SOP_BLK) sop_kernel(const float* __restrict__ feats,
                                                      float* __restrict__ out) {
    __shared__ float sf[SOP_BLK][DIM];
    __shared__ float sw2[SOP_BLK];
    __shared__ unsigned int isLast;

    const int tid = threadIdx.x;
    const int b   = blockIdx.x;
    const int p   = b * SOP_BLK + tid;

    float se = 0.0f, sw = 0.0f;
    #pragma unroll
    for (int s = 0; s < KSPLIT; s++) {
        se += g_se[s][p];
        sw += g_sw[s][p];
    }
    const float c4ln2 = 4.0f * 0.6931471805599453f;
    float cf = c4ln2 * sw / se;
    float w = 1.0f / (1.0f + __expf(-cf));
    sw2[tid] = w * w;

    const float4* fp = reinterpret_cast<const float4*>(feats) + p * 4;
    float4 f0 = fp[0], f1 = fp[1], f2 = fp[2], f3 = fp[3];
    sf[tid][0]  = f0.x; sf[tid][1]  = f0.y; sf[tid][2]  = f0.z; sf[tid][3]  = f0.w;
    sf[tid][4]  = f1.x; sf[tid][5]  = f1.y; sf[tid][6]  = f1.z; sf[tid][7]  = f1.w;
    sf[tid][8]  = f2.x; sf[tid][9]  = f2.y; sf[tid][10] = f2.z; sf[tid][11] = f2.w;
    sf[tid][12] = f3.x; sf[tid][13] = f3.y; sf[tid][14] = f3.z; sf[tid][15] = f3.w;
    __syncthreads();

    const int d = tid >> 4;
    const int e = tid & 15;
    float acc = 0.0f;
    #pragma unroll 8
    for (int i = 0; i < SOP_BLK; i++) {
        acc = fmaf(sw2[i] * sf[i][d], sf[i][e], acc);
    }
    g_Mpart[b][tid] = acc;

    // ---- last-block finalize (deterministic; counter self-resets) ----
    __threadfence();
    if (tid == 0) isLast = (atomicAdd(&g_cnt, 1u) == SOP_BLOCKS - 1) ? 1u : 0u;
    __syncthreads();
    if (isLast) {
        __threadfence();
        float v = 0.0f;
        #pragma unroll 8
        for (int bb = 0; bb < SOP_BLOCKS; bb++) v += g_Mpart[bb][tid];

        __syncthreads();          // sw2 reuse safe
        sw2[tid] = v * v;
        __syncthreads();
        #pragma unroll
        for (int o = 128; o > 0; o >>= 1) {
            if (tid < o) sw2[tid] += sw2[tid + o];
            __syncthreads();
        }
        float inv = 1.0f / sqrtf(sw2[0]);
        out[tid] = v * inv;
        if (tid == 0) g_cnt = 0;
    }
}

// ---------------------------------------------------------------------------
extern "C" void kernel_launch(void* const* d_in, const int* in_sizes, int n_in,
                              void* d_out, int out_size) {
    const float* feats = (const float*)d_in[0];
    float* out = (float*)d_out;

    attn_mma_kernel<<<KSPLIT * QT_TILES, TPB>>>(feats);
    sop_kernel<<<SOP_BLOCKS, SOP_BLK>>>(feats, out);
}

// round 14
// speedup vs baseline: 1.2751x; 1.0783x over previous
#include <cuda_runtime.h>
#include <cuda_bf16.h>
#include <cstdint>

#define NPTS 12288
#define DIM 16
#define KSPLIT 6
#define QT_TILES 96                     // 12288/128 query tiles
#define TPB 256
#define KEYS_PER_SPLIT (NPTS / KSPLIT)  // 2048
#define KEYTILE 512
#define TILES (KEYS_PER_SPLIT / KEYTILE)// 4
#define SOP_BPTS 64                     // points per sop block
#define SOP_BLOCKS (NPTS / SOP_BPTS)    // 192

// ---- scratch (__device__ globals; no allocation allowed) ------------------
__device__ uint32_t g_qa[NPTS * 8];         // queries, bf16x2, pre-scaled by 0.25*log2(e)
__device__ uint32_t g_kb[NPTS * 8];         // keys, bf16x2, unscaled
__device__ float g_se[KSPLIT][NPTS];        // exp-sum partials
__device__ float g_sw[KSPLIT][NPTS];        // exp*score-sum partials (log2-units)
__device__ float g_Mpart[SOP_BLOCKS][256];  // per-block SOP partials
__device__ unsigned int g_cnt = 0;          // last-block counter (self-resetting)

__device__ __forceinline__ float ex2_approx(float x) {
    float r; asm("ex2.approx.ftz.f32 %0, %1;" : "=f"(r) : "f"(x)); return r;
}

// ---------------------------------------------------------------------------
// Kernel 0: convert feats (f32) to bf16 row-major arrays (R9 version).
// One float4 per thread (192 blocks x 256 thr).
// g_qa = feats * 0.25*log2(e)  (A operand; MMA output = score in log2 units)
// g_kb = feats                 (B operand)
// ---------------------------------------------------------------------------
__global__ void convert_kernel(const float* __restrict__ feats) {
    const int i = blockIdx.x * 256 + threadIdx.x;   // float4 index, 0..49151
    const float sc = 0.25f * 1.4426950408889634f;
    float4 v = reinterpret_cast<const float4*>(feats)[i];
    __nv_bfloat162 qa0 = __floats2bfloat162_rn(v.x * sc, v.y * sc);
    __nv_bfloat162 qa1 = __floats2bfloat162_rn(v.z * sc, v.w * sc);
    __nv_bfloat162 kb0 = __floats2bfloat162_rn(v.x, v.y);
    __nv_bfloat162 kb1 = __floats2bfloat162_rn(v.z, v.w);
    uint2 qa = make_uint2(*reinterpret_cast<uint32_t*>(&qa0),
                          *reinterpret_cast<uint32_t*>(&qa1));
    uint2 kb = make_uint2(*reinterpret_cast<uint32_t*>(&kb0),
                          *reinterpret_cast<uint32_t*>(&kb1));
    reinterpret_cast<uint2*>(g_qa)[i] = qa;
    reinterpret_cast<uint2*>(g_kb)[i] = kb;
}

// ---------------------------------------------------------------------------
// Kernel 1: tensor-core attention row stats via warp-level mma.sync
// (exact R9 version — known 27.6us). Warp owns 16 queries (A frag, loaded
// once); loops over 512-key smem tiles (48B/key stride -> conflict-free).
// Per MMA: scores (16q x 8k) in d0..d3; epilogue e = 2^t; se += e;
// sw += e*t (fp32, pure MUFU). Quad shfl reduce at end.
// Identity: <ctx_q,f_q> = 4*ln2 * sw_q/se_q -> no ctx materialization.
// ---------------------------------------------------------------------------
__global__ void __launch_bounds__(TPB, 4) attn_mma_kernel() {
    __shared__ uint32_t sk[KEYTILE * 12];   // 24 KB, 48B per key (12 words)

    const int tid  = threadIdx.x;
    const int warp = tid >> 5;
    const int lane = tid & 31;
    const int g    = lane >> 2;             // 0..7
    const int tig  = lane & 3;              // 0..3
    const int qt    = blockIdx.x % QT_TILES;
    const int split = blockIdx.x / QT_TILES;

    const int q0 = qt * 128 + warp * 16 + g;
    const int q1 = q0 + 8;

    // A fragment (row-major 16x16 bf16): rows g/g+8, cols 2tig..2tig+1, +8
    const uint32_t a0 = g_qa[q0 * 8 + tig];
    const uint32_t a1 = g_qa[q1 * 8 + tig];
    const uint32_t a2 = g_qa[q0 * 8 + tig + 4];
    const uint32_t a3 = g_qa[q1 * 8 + tig + 4];

    float se0 = 0.0f, se1 = 0.0f, sw0 = 0.0f, sw1 = 0.0f;

    const int key0 = split * KEYS_PER_SPLIT;

    for (int tile = 0; tile < TILES; tile++) {
        __syncthreads();
        // stage 512 keys: src float4 f covers key f/2, half f&1 (32B/key)
        {
            const float4* src = reinterpret_cast<const float4*>(g_kb)
                              + (key0 + tile * KEYTILE) * 2;
            float4* dst = reinterpret_cast<float4*>(sk);
            #pragma unroll
            for (int f = tid; f < KEYTILE * 2; f += TPB) {
                int key = f >> 1, half = f & 1;
                dst[key * 3 + half] = src[f];
            }
        }
        __syncthreads();

        #pragma unroll 4
        for (int j = 0; j < KEYTILE / 8; j++) {
            const int kb = j * 8 + g;       // this thread's B-fragment key
            uint32_t b0 = sk[kb * 12 + tig];
            uint32_t b1 = sk[kb * 12 + tig + 4];

            float d0, d1, d2, d3;
            asm volatile(
                "mma.sync.aligned.m16n8k16.row.col.f32.bf16.bf16.f32 "
                "{%0,%1,%2,%3}, {%4,%5,%6,%7}, {%8,%9}, {%10,%11,%12,%13};"
                : "=f"(d0), "=f"(d1), "=f"(d2), "=f"(d3)
                : "r"(a0), "r"(a1), "r"(a2), "r"(a3), "r"(b0), "r"(b1),
                  "f"(0.0f), "f"(0.0f), "f"(0.0f), "f"(0.0f));

            // d0,d1: row g (keys 2tig,2tig+1); d2,d3: row g+8
            float e;
            e = ex2_approx(d0); se0 += e; sw0 = fmaf(e, d0, sw0);
            e = ex2_approx(d1); se0 += e; sw0 = fmaf(e, d1, sw0);
            e = ex2_approx(d2); se1 += e; sw1 = fmaf(e, d2, sw1);
            e = ex2_approx(d3); se1 += e; sw1 = fmaf(e, d3, sw1);
        }
    }

    // reduce across the 4 threads of each row-quad (tids 4g..4g+3)
    se0 += __shfl_xor_sync(0xffffffffu, se0, 1);
    se0 += __shfl_xor_sync(0xffffffffu, se0, 2);
    se1 += __shfl_xor_sync(0xffffffffu, se1, 1);
    se1 += __shfl_xor_sync(0xffffffffu, se1, 2);
    sw0 += __shfl_xor_sync(0xffffffffu, sw0, 1);
    sw0 += __shfl_xor_sync(0xffffffffu, sw0, 2);
    sw1 += __shfl_xor_sync(0xffffffffu, sw1, 1);
    sw1 += __shfl_xor_sync(0xffffffffu, sw1, 2);

    if (tig == 0) {
        g_se[split][q0] = se0;
        g_sw[split][q0] = sw0;
        g_se[split][q1] = se1;
        g_sw[split][q1] = sw1;
    }
}

// ---------------------------------------------------------------------------
// Kernel 2: SOP, restructured for LATENCY (old version: 48 blocks, 256-deep
// serial fmaf chains, 11.6us at occ 12%). Now: 192 blocks x 64 points, and
// 4 independent accumulators (16 deps each). w = sigmoid(4*ln2 * sw/se);
// M_b = sum_i w_i^2 f_i f_i^T over this block's 64 points. LAST block
// (atomic counter) reduces the 192 partials with 4-way ILP, L2-normalizes,
// writes the 256-float output, resets the counter.
// (topK=1 -> all points kept; /k cancels in the L2-normalize.)
// ---------------------------------------------------------------------------
__global__ void __launch_bounds__(256) sop_kernel(const float* __restrict__ feats,
                                                  float* __restrict__ out) {
    __shared__ float sf[SOP_BPTS][DIM];
    __shared__ float sw2[SOP_BPTS];
    __shared__ float red[256];
    __shared__ unsigned int isLast;

    const int tid = threadIdx.x;
    const int b   = blockIdx.x;

    // head: w^2 for this block's 64 points (threads 0..63)
    if (tid < SOP_BPTS) {
        const int p = b * SOP_BPTS + tid;
        float se = 0.0f, sw = 0.0f;
        #pragma unroll
        for (int s = 0; s < KSPLIT; s++) {
            se += g_se[s][p];
            sw += g_sw[s][p];
        }
        const float c4ln2 = 4.0f * 0.6931471805599453f;
        float cf = c4ln2 * sw / se;
        float w = 1.0f / (1.0f + __expf(-cf));
        sw2[tid] = w * w;
    }
    // feats for 64 points: 256 float4 loads, one per thread
    {
        float4 v = reinterpret_cast<const float4*>(feats)[b * 256 + tid];
        reinterpret_cast<float4*>(&sf[tid >> 2][(tid & 3) * 4])[0] = v;
    }
    __syncthreads();

    // thread t owns entry (d, e); 4 independent chains over the 64 points
    const int d = tid >> 4;
    const int e = tid & 15;
    float a0 = 0.f, a1 = 0.f, a2 = 0.f, a3 = 0.f;
    #pragma unroll
    for (int i = 0; i < SOP_BPTS; i += 4) {
        a0 = fmaf(sw2[i + 0] * sf[i + 0][d], sf[i + 0][e], a0);
        a1 = fmaf(sw2[i + 1] * sf[i + 1][d], sf[i + 1][e], a1);
        a2 = fmaf(sw2[i + 2] * sf[i + 2][d], sf[i + 2][e], a2);
        a3 = fmaf(sw2[i + 3] * sf[i + 3][d], sf[i + 3][e], a3);
    }
    g_Mpart[b][tid] = (a0 + a1) + (a2 + a3);

    // ---- last-block finalize (deterministic; counter self-resets) ----
    __threadfence();
    if (tid == 0) isLast = (atomicAdd(&g_cnt, 1u) == SOP_BLOCKS - 1) ? 1u : 0u;
    __syncthreads();
    if (isLast) {
        __threadfence();
        float v0 = 0.f, v1 = 0.f, v2 = 0.f, v3 = 0.f;
        #pragma unroll 4
        for (int bb = 0; bb < SOP_BLOCKS; bb += 4) {
            v0 += g_Mpart[bb + 0][tid];
            v1 += g_Mpart[bb + 1][tid];
            v2 += g_Mpart[bb + 2][tid];
            v3 += g_Mpart[bb + 3][tid];
        }
        float v = (v0 + v1) + (v2 + v3);

        red[tid] = v * v;
        __syncthreads();
        #pragma unroll
        for (int o = 128; o > 0; o >>= 1) {
            if (tid < o) red[tid] += red[tid + o];
            __syncthreads();
        }
        float inv = 1.0f / sqrtf(red[0]);
        out[tid] = v * inv;
        if (tid == 0) g_cnt = 0;
    }
}

// ---------------------------------------------------------------------------
extern "C" void kernel_launch(void* const* d_in, const int* in_sizes, int n_in,
                              void* d_out, int out_size) {
    const float* feats = (const float*)d_in[0];
    float* out = (float*)d_out;

    convert_kernel<<<NPTS * 4 / 256, 256>>>(feats);
    attn_mma_kernel<<<KSPLIT * QT_TILES, TPB>>>();
    sop_kernel<<<SOP_BLOCKS, 256>>>(feats, out);
}

// round 15
// speedup vs baseline: 1.3449x; 1.0548x over previous
#include <cuda_runtime.h>
#include <cuda_bf16.h>
#include <cstdint>

#define NPTS 12288
#define DIM 16
#define KSPLIT 6
#define QT_TILES 96                     // 12288/128 query tiles
#define TPB 256
#define KEYS_PER_SPLIT (NPTS / KSPLIT)  // 2048
#define KEYTILE 512
#define TILES (KEYS_PER_SPLIT / KEYTILE)// 4
#define SOP_BPTS 128                    // points per sop block
#define SOP_BLOCKS (NPTS / SOP_BPTS)    // 96

// ---- scratch (__device__ globals; no allocation allowed) ------------------
__device__ uint32_t g_kb[NPTS * 8];         // keys, bf16x2, unscaled
__device__ float g_se[KSPLIT][NPTS];        // exp-sum partials
__device__ float g_sw[KSPLIT][NPTS];        // exp*score-sum partials (log2-units)
__device__ float g_Mpart[SOP_BLOCKS][256];  // per-block SOP partials
__device__ unsigned int g_cnt = 0;          // last-block counter (self-resetting)

__device__ __forceinline__ float ex2_approx(float x) {
    float r; asm("ex2.approx.ftz.f32 %0, %1;" : "=f"(r) : "f"(x)); return r;
}
__device__ __forceinline__ uint32_t bf2_u32(__nv_bfloat162 v) {
    return *reinterpret_cast<uint32_t*>(&v);
}

// ---------------------------------------------------------------------------
// Kernel 0: convert feats (f32) to the bf16 KEY array only (queries are
// converted in-kernel by attn). One float4 -> one uint2 per thread.
// ---------------------------------------------------------------------------
__global__ void convert_kernel(const float* __restrict__ feats) {
    const int i = blockIdx.x * 256 + threadIdx.x;   // float4 index, 0..49151
    float4 v = reinterpret_cast<const float4*>(feats)[i];
    uint2 kb = make_uint2(bf2_u32(__floats2bfloat162_rn(v.x, v.y)),
                          bf2_u32(__floats2bfloat162_rn(v.z, v.w)));
    reinterpret_cast<uint2*>(g_kb)[i] = kb;
}

// ---------------------------------------------------------------------------
// Kernel 1: tensor-core attention row stats via warp-level mma.sync
// (mainloop identical to the proven R9 kernel). Warp owns 16 queries; A
// fragments built once from feats (f32 -> scaled bf16). Loops over 512-key
// smem tiles (48B/key stride -> conflict-free). Per MMA: scores (16q x 8k)
// in d0..d3; epilogue e = 2^t; se += e; sw += e*t (fp32, pure MUFU).
// Quad shfl reduce at end. Identity: <ctx_q,f_q> = 4*ln2 * sw_q/se_q.
// ---------------------------------------------------------------------------
__global__ void __launch_bounds__(TPB, 4) attn_mma_kernel(const float* __restrict__ feats) {
    __shared__ uint32_t sk[KEYTILE * 12];   // 24 KB, 48B per key (12 words)

    const int tid  = threadIdx.x;
    const int warp = tid >> 5;
    const int lane = tid & 31;
    const int g    = lane >> 2;             // 0..7
    const int tig  = lane & 3;              // 0..3
    const int qt    = blockIdx.x % QT_TILES;
    const int split = blockIdx.x / QT_TILES;

    const int q0 = qt * 128 + warp * 16 + g;
    const int q1 = q0 + 8;

    // A fragments straight from feats (scaled f32 -> bf16x2)
    const float sc = 0.25f * 1.4426950408889634f;
    const float2* f2 = reinterpret_cast<const float2*>(feats);
    float2 v00 = f2[q0 * 8 + tig];
    float2 v02 = f2[q0 * 8 + tig + 4];
    float2 v10 = f2[q1 * 8 + tig];
    float2 v12 = f2[q1 * 8 + tig + 4];
    const uint32_t a0 = bf2_u32(__floats2bfloat162_rn(v00.x * sc, v00.y * sc));
    const uint32_t a1 = bf2_u32(__floats2bfloat162_rn(v10.x * sc, v10.y * sc));
    const uint32_t a2 = bf2_u32(__floats2bfloat162_rn(v02.x * sc, v02.y * sc));
    const uint32_t a3 = bf2_u32(__floats2bfloat162_rn(v12.x * sc, v12.y * sc));

    float se0 = 0.0f, se1 = 0.0f, sw0 = 0.0f, sw1 = 0.0f;

    const int key0 = split * KEYS_PER_SPLIT;

    for (int tile = 0; tile < TILES; tile++) {
        __syncthreads();
        // stage 512 keys: src float4 f covers key f/2, half f&1 (32B/key)
        {
            const float4* src = reinterpret_cast<const float4*>(g_kb)
                              + (key0 + tile * KEYTILE) * 2;
            float4* dst = reinterpret_cast<float4*>(sk);
            #pragma unroll
            for (int f = tid; f < KEYTILE * 2; f += TPB) {
                int key = f >> 1, half = f & 1;
                dst[key * 3 + half] = src[f];
            }
        }
        __syncthreads();

        #pragma unroll 4
        for (int j = 0; j < KEYTILE / 8; j++) {
            const int kb = j * 8 + g;       // this thread's B-fragment key
            uint32_t b0 = sk[kb * 12 + tig];
            uint32_t b1 = sk[kb * 12 + tig + 4];

            float d0, d1, d2, d3;
            asm volatile(
                "mma.sync.aligned.m16n8k16.row.col.f32.bf16.bf16.f32 "
                "{%0,%1,%2,%3}, {%4,%5,%6,%7}, {%8,%9}, {%10,%11,%12,%13};"
                : "=f"(d0), "=f"(d1), "=f"(d2), "=f"(d3)
                : "r"(a0), "r"(a1), "r"(a2), "r"(a3), "r"(b0), "r"(b1),
                  "f"(0.0f), "f"(0.0f), "f"(0.0f), "f"(0.0f));

            // d0,d1: row g (keys 2tig,2tig+1); d2,d3: row g+8
            float e;
            e = ex2_approx(d0); se0 += e; sw0 = fmaf(e, d0, sw0);
            e = ex2_approx(d1); se0 += e; sw0 = fmaf(e, d1, sw0);
            e = ex2_approx(d2); se1 += e; sw1 = fmaf(e, d2, sw1);
            e = ex2_approx(d3); se1 += e; sw1 = fmaf(e, d3, sw1);
        }
    }

    // reduce across the 4 threads of each row-quad (tids 4g..4g+3)
    se0 += __shfl_xor_sync(0xffffffffu, se0, 1);
    se0 += __shfl_xor_sync(0xffffffffu, se0, 2);
    se1 += __shfl_xor_sync(0xffffffffu, se1, 1);
    se1 += __shfl_xor_sync(0xffffffffu, se1, 2);
    sw0 += __shfl_xor_sync(0xffffffffu, sw0, 1);
    sw0 += __shfl_xor_sync(0xffffffffu, sw0, 2);
    sw1 += __shfl_xor_sync(0xffffffffu, sw1, 1);
    sw1 += __shfl_xor_sync(0xffffffffu, sw1, 2);

    if (tig == 0) {
        g_se[split][q0] = se0;
        g_sw[split][q0] = sw0;
        g_se[split][q1] = se1;
        g_sw[split][q1] = sw1;
    }
}

// ---------------------------------------------------------------------------
// Kernel 2: SOP. 96 blocks x 128 points; 8 independent fmaf chains (16 deps).
// w = sigmoid(4*ln2 * sw/se); M_b = sum_i w_i^2 f_i f_i^T. LAST block
// (atomic counter) reduces the 96 partials with 8-way MLP (12 L2-latency
// batches), L2-normalizes, writes the 256-float output, resets the counter.
// (topK=1 -> all points kept; /k cancels in the L2-normalize.)
// ---------------------------------------------------------------------------
__global__ void __launch_bounds__(256) sop_kernel(const float* __restrict__ feats,
                                                  float* __restrict__ out) {
    __shared__ float sf[SOP_BPTS][DIM];
    __shared__ float sw2[SOP_BPTS];
    __shared__ float red[256];
    __shared__ unsigned int isLast;

    const int tid = threadIdx.x;
    const int b   = blockIdx.x;

    // head: w^2 for this block's 128 points (threads 0..127)
    if (tid < SOP_BPTS) {
        const int p = b * SOP_BPTS + tid;
        float se = 0.0f, sw = 0.0f;
        #pragma unroll
        for (int s = 0; s < KSPLIT; s++) {
            se += g_se[s][p];
            sw += g_sw[s][p];
        }
        const float c4ln2 = 4.0f * 0.6931471805599453f;
        float cf = c4ln2 * sw / se;
        float w = 1.0f / (1.0f + __expf(-cf));
        sw2[tid] = w * w;
    }
    // feats for 128 points: 512 float4 loads, two per thread
    {
        const float4* src = reinterpret_cast<const float4*>(feats) + b * 512;
        #pragma unroll
        for (int k = 0; k < 2; k++) {
            int idx = tid + k * 256;
            float4 v = src[idx];
            reinterpret_cast<float4*>(&sf[idx >> 2][(idx & 3) * 4])[0] = v;
        }
    }
    __syncthreads();

    // thread t owns entry (d, e); 8 independent chains over the 128 points
    const int d = tid >> 4;
    const int e = tid & 15;
    float a0 = 0.f, a1 = 0.f, a2 = 0.f, a3 = 0.f;
    float a4 = 0.f, a5 = 0.f, a6 = 0.f, a7 = 0.f;
    #pragma unroll
    for (int i = 0; i < SOP_BPTS; i += 8) {
        a0 = fmaf(sw2[i + 0] * sf[i + 0][d], sf[i + 0][e], a0);
        a1 = fmaf(sw2[i + 1] * sf[i + 1][d], sf[i + 1][e], a1);
        a2 = fmaf(sw2[i + 2] * sf[i + 2][d], sf[i + 2][e], a2);
        a3 = fmaf(sw2[i + 3] * sf[i + 3][d], sf[i + 3][e], a3);
        a4 = fmaf(sw2[i + 4] * sf[i + 4][d], sf[i + 4][e], a4);
        a5 = fmaf(sw2[i + 5] * sf[i + 5][d], sf[i + 5][e], a5);
        a6 = fmaf(sw2[i + 6] * sf[i + 6][d], sf[i + 6][e], a6);
        a7 = fmaf(sw2[i + 7] * sf[i + 7][d], sf[i + 7][e], a7);
    }
    g_Mpart[b][tid] = ((a0 + a1) + (a2 + a3)) + ((a4 + a5) + (a6 + a7));

    // ---- last-block finalize (deterministic; counter self-resets) ----
    __threadfence();
    if (tid == 0) isLast = (atomicAdd(&g_cnt, 1u) == SOP_BLOCKS - 1) ? 1u : 0u;
    __syncthreads();
    if (isLast) {
        __threadfence();
        float v0 = 0.f, v1 = 0.f, v2 = 0.f, v3 = 0.f;
        float v4 = 0.f, v5 = 0.f, v6 = 0.f, v7 = 0.f;
        #pragma unroll
        for (int bb = 0; bb < SOP_BLOCKS; bb += 8) {
            v0 += g_Mpart[bb + 0][tid];
            v1 += g_Mpart[bb + 1][tid];
            v2 += g_Mpart[bb + 2][tid];
            v3 += g_Mpart[bb + 3][tid];
            v4 += g_Mpart[bb + 4][tid];
            v5 += g_Mpart[bb + 5][tid];
            v6 += g_Mpart[bb + 6][tid];
            v7 += g_Mpart[bb + 7][tid];
        }
        float v = ((v0 + v1) + (v2 + v3)) + ((v4 + v5) + (v6 + v7));

        red[tid] = v * v;
        __syncthreads();
        #pragma unroll
        for (int o = 128; o > 0; o >>= 1) {
            if (tid < o) red[tid] += red[tid + o];
            __syncthreads();
        }
        float inv = 1.0f / sqrtf(red[0]);
        out[tid] = v * inv;
        if (tid == 0) g_cnt = 0;
    }
}

// ---------------------------------------------------------------------------
extern "C" void kernel_launch(void* const* d_in, const int* in_sizes, int n_in,
                              void* d_out, int out_size) {
    const float* feats = (const float*)d_in[0];
    float* out = (float*)d_out;

    convert_kernel<<<NPTS * 4 / 256, 256>>>(feats);
    attn_mma_kernel<<<KSPLIT * QT_TILES, TPB>>>(feats);
    sop_kernel<<<SOP_BLOCKS, 256>>>(feats, out);
}